// round 16
// baseline (speedup 1.0000x reference)
#include <cuda_runtime.h>
#include <cuda_bf16.h>
#include <cuda_fp16.h>
#include <math.h>

// Problem constants (fixed by the dataset)
#define N_NODES   100000
#define E_EDGES   1600000
#define HDIM      64
#define OUT_DIM   32
#define NUM_GRAPHS 64

#define SCAN_TILE 1024
#define NB_SCAN   ((N_NODES + SCAN_TILE - 1) / SCAN_TILE)   // 98
#define EDGE_BLOCKS ((E_EDGES + 511) / 512)                  // 3125
#define PROP_GRID  ((N_NODES * 32 + 255) / 256)              // 12500
#define SCAN_FLAG  (1 << 30)

// tensor GEMM geometry (mma.sync path)
#define TILE_M    64             // per-iteration M tile
#define N2        128            // Wi|Wr side by side
#define KSTEPS    4              // 4 k-steps of 16 over K=64, x2 B segments
#define A_STRIDE  72             // bf16 elems per A row (64 + 8 pad)
#define B_STRIDE  136            // bf16 elems per B n-row (128 k + 8 pad)
#define RAW_F32_STRIDE 272       // bytes per raw fp32 row (256 + 16 pad)
#define RAW_F16_STRIDE 144       // bytes per raw fp16 row (128 + 16 pad)
#define RAW_BYTES (TILE_M * RAW_F32_STRIDE)   // 17408 (max of both)
#define A_BYTES   (TILE_M * A_STRIDE * 2)     // 9216
#define B_BYTES   (N2 * B_STRIDE * 2)         // 34816
#define GEMM_SMEM (RAW_BYTES + A_BYTES + B_BYTES)   // 61440
#define GEMM_TILES ((N_NODES + TILE_M - 1) / TILE_M)   // 1563
#define GEMM_GRID  444           // persistent: 3 CTAs/SM x 148 SMs
#define WPREP_ELEMS (2 * N2 * B_STRIDE)

// ---------------- scratch (static device globals; no allocation) ------------
__device__ int   g_deg[N_NODES];
__device__ int   g_rowptr[N_NODES + 1];
__device__ int   g_bsums[NB_SCAN];
__device__ int   g_csr[E_EDGES];
__device__ int   g_perm[E_EDGES];
__device__ __align__(16) float  g_dinv[N_NODES];
__device__ __align__(16) __half g_t [N_NODES * HDIM];    // fp16 propagate source
__device__ __align__(16) __half g_r [N_NODES * HDIM];    // fp16 root term
__device__ __align__(16) __half g_h1[N_NODES * HDIM];    // fp16 layer-1 output
__device__ __align__(16) float  g_pool[NUM_GRAPHS * HDIM];
__device__ __align__(16) unsigned short g_wb[2][N2 * B_STRIDE];  // n-major B images

// ---------------- PTX helpers ------------------------------------------------
__device__ __forceinline__ unsigned smem_u32(const void* p) {
    unsigned a;
    asm("{ .reg .u64 t; cvta.to.shared.u64 t, %1; cvt.u32.u64 %0, t; }" : "=r"(a) : "l"(p));
    return a;
}
__device__ __forceinline__ void ldsm_x4(unsigned& r0, unsigned& r1, unsigned& r2, unsigned& r3,
                                        unsigned addr) {
    asm volatile("ldmatrix.sync.aligned.m8n8.x4.shared.b16 {%0,%1,%2,%3}, [%4];"
                 : "=r"(r0), "=r"(r1), "=r"(r2), "=r"(r3) : "r"(addr));
}
__device__ __forceinline__ void mma_bf16(float* d, const unsigned* a, const unsigned* b) {
    asm volatile(
        "mma.sync.aligned.m16n8k16.row.col.f32.bf16.bf16.f32 "
        "{%0,%1,%2,%3}, {%4,%5,%6,%7}, {%8,%9}, {%0,%1,%2,%3};"
        : "+f"(d[0]), "+f"(d[1]), "+f"(d[2]), "+f"(d[3])
        : "r"(a[0]), "r"(a[1]), "r"(a[2]), "r"(a[3]), "r"(b[0]), "r"(b[1]));
}
__device__ __forceinline__ void cp_async16(unsigned dst, const void* src, int src_bytes) {
    asm volatile("cp.async.ca.shared.global [%0], [%1], 16, %2;"
                 :: "r"(dst), "l"(src), "r"(src_bytes) : "memory");
}
__device__ __forceinline__ void cp_commit() {
    asm volatile("cp.async.commit_group;" ::: "memory");
}
__device__ __forceinline__ void cp_wait0() {
    asm volatile("cp.async.wait_group 0;" ::: "memory");
}

// ---------------- count_deg + wprep + bsums-clear (disjoint blocks) ----------
__global__ void __launch_bounds__(512) count_wprep_kernel(
    const int* __restrict__ col, int E,
    const float* __restrict__ w1i, const float* __restrict__ w1r,
    const float* __restrict__ w2i, const float* __restrict__ w2r)
{
    int b = blockIdx.x;
    if (b < EDGE_BLOCKS) {
        int i = b * 512 + threadIdx.x;
        if (i < E) g_perm[i] = atomicAdd(&g_deg[col[i]], 1);
    } else {
        int idx = (b - EDGE_BLOCKS) * 512 + threadIdx.x;
        if (b == EDGE_BLOCKS && threadIdx.x < NB_SCAN) g_bsums[threadIdx.x] = 0;
        if (idx >= WPREP_ELEMS) return;
        int layer = idx / (N2 * B_STRIDE);
        int rem = idx % (N2 * B_STRIDE);
        int n = rem / B_STRIDE;        // output col (0..63 Wi, 64..127 Wr)
        int k = rem % B_STRIDE;        // 0..63 Bh, 64..127 Bl, >=128 pad
        __nv_bfloat16 val = __float2bfloat16(0.f);
        if (k < 128) {
            int seg = k >> 6, kk = k & 63;
            const float* W = (n < 64) ? (layer ? w2i : w1i) : (layer ? w2r : w1r);
            float w = W[kk * 64 + (n & 63)];
            __nv_bfloat16 hi = __float2bfloat16(w);
            val = seg ? __float2bfloat16(w - __bfloat162float(hi)) : hi;
        }
        g_wb[layer][rem] = *reinterpret_cast<unsigned short*>(&val);
    }
}

// ---------------- single-pass scan (publish + spin lookback) -----------------
__global__ void __launch_bounds__(256) scan_kernel() {
    int b = blockIdx.x;
    int tid = threadIdx.x;
    int lane = tid & 31, warp = tid >> 5;

    int base = b * SCAN_TILE + tid * 4;
    int d[4];
#pragma unroll
    for (int j = 0; j < 4; j++) {
        int idx = base + j;
        d[j] = (idx < N_NODES) ? g_deg[idx] : 0;
    }
    int tsum = d[0] + d[1] + d[2] + d[3];
    int incl = tsum;
    for (int o = 1; o < 32; o <<= 1) {
        int v = __shfl_up_sync(0xffffffffu, incl, o);
        if (lane >= o) incl += v;
    }
    __shared__ int wsum[8];
    if (lane == 31) wsum[warp] = incl;
    __syncthreads();

    if (tid == 0) {
        int total = 0;
        for (int w = 0; w < 8; w++) total += wsum[w];
        atomicExch(&g_bsums[b], total | SCAN_FLAG);
    }

    int pre = 0;
    if (tid < b) {
        volatile int* p = &g_bsums[tid];
        int v;
        do { v = *p; } while ((v & SCAN_FLAG) == 0);
        pre = v & ~SCAN_FLAG;
    }
    for (int o = 16; o > 0; o >>= 1) pre += __shfl_down_sync(0xffffffffu, pre, o);
    __shared__ int ws2[8];
    if (lane == 0) ws2[warp] = pre;
    __syncthreads();
    __shared__ int s_boff;
    if (tid == 0) {
        int t = 0;
        for (int w = 0; w < 8; w++) t += ws2[w];
        s_boff = t;
    }
    __syncthreads();

    int excl = incl - tsum;
    int woff = 0;
    for (int w = 0; w < warp; w++) woff += wsum[w];
    int off = s_boff + woff + excl;
#pragma unroll
    for (int j = 0; j < 4; j++) {
        int idx = base + j;
        if (idx < N_NODES) {
            g_rowptr[idx] = off;
            g_dinv[idx]   = (d[j] > 0) ? rsqrtf((float)d[j]) : 0.0f;
            off += d[j];
        }
    }
    if (b == NB_SCAN - 1 && tid == 255) g_rowptr[N_NODES] = off;
}

// atomic-free fill using precomputed slots
__global__ void __launch_bounds__(512) fill_csr_kernel(const int* __restrict__ row,
                                                       const int* __restrict__ col, int E) {
    int i = blockIdx.x * 512 + threadIdx.x;
    if (i < E) g_csr[g_rowptr[col[i]] + g_perm[i]] = row[i];
}

// ---------------- persistent, pipelined mma.sync dual GEMM -------------------
template <typename TIN>
__global__ void __launch_bounds__(256, 3) gemm_tc_kernel(
    const TIN* __restrict__ X, int layer, int n)
{
    extern __shared__ char dsm[];
    char*          raw = dsm;                                 // RAW_BYTES
    __nv_bfloat16* sA  = (__nv_bfloat16*)(dsm + RAW_BYTES);   // [64][A_STRIDE]
    __nv_bfloat16* sB  = (__nv_bfloat16*)(dsm + RAW_BYTES + A_BYTES);

    int tid = threadIdx.x;
    int wid = tid >> 5, lane = tid & 31;
    unsigned rawu = smem_u32(raw);

    const bool F32 = (sizeof(TIN) == 4);
    const int RAW_STRIDE = F32 ? RAW_F32_STRIDE : RAW_F16_STRIDE;
    const int ROW_BYTES  = F32 ? 256 : 128;
    const int CHUNKS     = TILE_M * (ROW_BYTES / 16);   // 1024 or 512

    // prefetch first tile
    {
        int tile0 = blockIdx.x;
        int row0 = tile0 * TILE_M;
        for (int c = tid; c < CHUNKS; c += 256) {
            int r = c / (ROW_BYTES / 16);
            int o = c % (ROW_BYTES / 16);
            int grow = row0 + r;
            int ok = (grow < n) ? 16 : 0;
            const char* src = (const char*)X + (size_t)(ok ? grow : 0) * ROW_BYTES + o * 16;
            cp_async16(rawu + r * RAW_STRIDE + o * 16, src, ok);
        }
        cp_commit();
    }

    // stage B' image once (35KB from L2)
    {
        const uint4* src = (const uint4*)g_wb[layer];
        uint4* dst = (uint4*)sB;
        for (int i = tid; i < B_BYTES / 16; i += 256) dst[i] = src[i];
    }

    int mwarp = (wid & 3) * 16;      // 16-row m-group
    int nwarp = (wid >> 2);          // 0 -> T cols, 1 -> R cols
    int nbase = nwarp * 64;

    unsigned aAbase, aBbase;
    {
        unsigned sAu = smem_u32(sA);
        unsigned sBu = smem_u32(sB);
        aAbase = sAu + (unsigned)((mwarp + (lane & 15)) * A_STRIDE * 2 + (lane >> 4) * 16);
        int brow = nbase + ((lane >> 4) & 1) * 8 + (lane & 7);
        int bcol = ((lane >> 3) & 1) * 8;
        aBbase = sBu + (unsigned)(brow * B_STRIDE * 2 + bcol * 2);
    }

    int ar = tid >> 2;               // A-convert: row 0..63
    int kq = tid & 3;                // k quarter
    unsigned* arow = (unsigned*)(sA + ar * A_STRIDE);

    for (int tile = blockIdx.x; tile < GEMM_TILES; tile += GEMM_GRID) {
        int row0 = tile * TILE_M;

        cp_wait0();
        __syncthreads();   // raw[tile] visible; prior mainloop done (sA reuse safe)

        // convert raw -> Ah bf16 in sA
        if (F32) {
            const float4* rrow = (const float4*)(raw + ar * RAW_F32_STRIDE);
#pragma unroll
            for (int q = 0; q < 4; q++) {
                float4 v = rrow[kq * 4 + q];
                int k0 = kq * 16 + q * 4;
#pragma unroll
                for (int h = 0; h < 2; h++) {
                    float a = h ? v.z : v.x;
                    float b = h ? v.w : v.y;
                    __nv_bfloat162 ph;
                    ph.x = __float2bfloat16(a);
                    ph.y = __float2bfloat16(b);
                    arow[(k0 + h * 2) >> 1] = *reinterpret_cast<unsigned*>(&ph);
                }
            }
        } else {
            const uint4* rrow = (const uint4*)(raw + ar * RAW_F16_STRIDE);
#pragma unroll
            for (int q = 0; q < 2; q++) {
                uint4 v = rrow[kq * 2 + q];
                unsigned comp[4] = {v.x, v.y, v.z, v.w};
                int k0 = kq * 16 + q * 8;
#pragma unroll
                for (int u = 0; u < 4; u++) {
                    __half2 hv = *reinterpret_cast<__half2*>(&comp[u]);
                    float2 f = __half22float2(hv);
                    __nv_bfloat162 ph;
                    ph.x = __float2bfloat16(f.x);
                    ph.y = __float2bfloat16(f.y);
                    arow[(k0 + u * 2) >> 1] = *reinterpret_cast<unsigned*>(&ph);
                }
            }
        }
        __syncthreads();   // sA ready, raw fully consumed

        // prefetch next tile's raw rows (overlaps mainloop + epilogue)
        int ntile = tile + GEMM_GRID;
        if (ntile < GEMM_TILES) {
            int nrow0 = ntile * TILE_M;
            for (int c = tid; c < CHUNKS; c += 256) {
                int r = c / (ROW_BYTES / 16);
                int o = c % (ROW_BYTES / 16);
                int grow = nrow0 + r;
                int ok = (grow < n) ? 16 : 0;
                const char* src = (const char*)X + (size_t)(ok ? grow : 0) * ROW_BYTES + o * 16;
                cp_async16(rawu + r * RAW_STRIDE + o * 16, src, ok);
            }
        }
        cp_commit();

        float acc[8][4];
#pragma unroll
        for (int j = 0; j < 8; j++)
#pragma unroll
            for (int c = 0; c < 4; c++) acc[j][c] = 0.f;

#pragma unroll
        for (int ks = 0; ks < KSTEPS; ks++) {
            unsigned a[4];
            ldsm_x4(a[0], a[1], a[2], a[3], aAbase + (unsigned)(ks * 32));
#pragma unroll
            for (int seg = 0; seg < 2; seg++) {
                unsigned b[8][2];
#pragma unroll
                for (int j = 0; j < 4; j++) {
                    unsigned r0, r1, r2, r3;
                    ldsm_x4(r0, r1, r2, r3,
                            aBbase + (unsigned)(j * 16 * B_STRIDE * 2 + (seg * 64 + ks * 16) * 2));
                    b[2 * j][0] = r0; b[2 * j][1] = r1;
                    b[2 * j + 1][0] = r2; b[2 * j + 1][1] = r3;
                }
#pragma unroll
                for (int j = 0; j < 8; j++)
                    mma_bf16(acc[j], a, b[j]);
            }
        }

        // epilogue: T (dinv-scaled, fp16) and R (fp16)
        {
            int r0 = row0 + mwarp + (lane >> 2);
            int r1 = r0 + 8;
            if (nwarp == 0) {
                float dv0 = (r0 < n) ? g_dinv[r0] : 0.f;
                float dv1 = (r1 < n) ? g_dinv[r1] : 0.f;
#pragma unroll
                for (int j = 0; j < 8; j++) {
                    int c = j * 8 + (lane & 3) * 2;
                    if (r0 < n)
                        *(__half2*)(g_t + (size_t)r0 * 64 + c) =
                            __floats2half2_rn(acc[j][0] * dv0, acc[j][1] * dv0);
                    if (r1 < n)
                        *(__half2*)(g_t + (size_t)r1 * 64 + c) =
                            __floats2half2_rn(acc[j][2] * dv1, acc[j][3] * dv1);
                }
            } else {
#pragma unroll
                for (int j = 0; j < 8; j++) {
                    int c = j * 8 + (lane & 3) * 2;
                    if (r0 < n)
                        *(__half2*)(g_r + (size_t)r0 * 64 + c) =
                            __floats2half2_rn(acc[j][0], acc[j][1]);
                    if (r1 < n)
                        *(__half2*)(g_r + (size_t)r1 * 64 + c) =
                            __floats2half2_rn(acc[j][2], acc[j][3]);
                }
            }
        }
    }
}

// ---------------- propagate + root + bias + relu (+ pool) -------------------
template <int LAYER>
__global__ void __launch_bounds__(256) prop_combine_kernel(
    const float* __restrict__ bias, const int* __restrict__ batch)
{
    __shared__ float pacc[64];
    int tid = threadIdx.x;
    if (LAYER == 1) {
        if (tid < 64) pacc[tid] = 0.f;
        __syncthreads();
    }

    int warp = (blockIdx.x * blockDim.x + tid) >> 5;
    int lane = tid & 31;
    int node = warp;

    if (node < N_NODES) {
        int s = g_rowptr[node];
        int e = g_rowptr[node + 1];

        const __half2* T2 = (const __half2*)g_t;
        float2 acc0 = make_float2(0.f, 0.f);
        float2 acc1 = make_float2(0.f, 0.f);
        float2 acc2 = make_float2(0.f, 0.f);
        float2 acc3 = make_float2(0.f, 0.f);

        int i = s;
        for (; i + 3 < e; i += 4) {
            int s0 = __ldg(&g_csr[i]);
            int s1 = __ldg(&g_csr[i + 1]);
            int s2 = __ldg(&g_csr[i + 2]);
            int s3 = __ldg(&g_csr[i + 3]);
            float2 v0 = __half22float2(T2[(size_t)s0 * 32 + lane]);
            float2 v1 = __half22float2(T2[(size_t)s1 * 32 + lane]);
            float2 v2 = __half22float2(T2[(size_t)s2 * 32 + lane]);
            float2 v3 = __half22float2(T2[(size_t)s3 * 32 + lane]);
            acc0.x += v0.x; acc0.y += v0.y;
            acc1.x += v1.x; acc1.y += v1.y;
            acc2.x += v2.x; acc2.y += v2.y;
            acc3.x += v3.x; acc3.y += v3.y;
        }
        for (; i < e; i++) {
            int s0 = __ldg(&g_csr[i]);
            float2 v0 = __half22float2(T2[(size_t)s0 * 32 + lane]);
            acc0.x += v0.x; acc0.y += v0.y;
        }
        acc0.x += acc1.x + acc2.x + acc3.x;
        acc0.y += acc1.y + acc2.y + acc3.y;

        float dv = g_dinv[node];
        float2 r = __half22float2(((const __half2*)g_r)[(size_t)node * 32 + lane]);
        float bx = bias[2 * lane], by = bias[2 * lane + 1];
        float hx = fmaf(dv, acc0.x, r.x + bx);
        float hy = fmaf(dv, acc0.y, r.y + by);
        hx = hx > 0.f ? hx : 0.f;
        hy = hy > 0.f ? hy : 0.f;

        if (LAYER == 0) {
            ((__half2*)g_h1)[(size_t)node * 32 + lane] = __floats2half2_rn(hx, hy);
        } else {
            int gme = __ldg(&batch[node]);
            int g0  = __ldg(&batch[blockIdx.x * 8]);
            if (gme == g0) {
                atomicAdd(&pacc[2 * lane], hx);
                atomicAdd(&pacc[2 * lane + 1], hy);
            } else {
                atomicAdd(&g_pool[gme * 64 + 2 * lane], hx);
                atomicAdd(&g_pool[gme * 64 + 2 * lane + 1], hy);
            }
        }
    }

    if (LAYER == 1) {
        __syncthreads();
        if (tid < 64) {
            int g0 = __ldg(&batch[blockIdx.x * 8]);
            atomicAdd(&g_pool[g0 * 64 + tid], pacc[tid]);
        }
    }
}

// ---------------- final FC on pooled means -----------------------------------
__device__ __forceinline__ int lbound_i(const int* a, int n, int key) {
    int lo = 0, hi = n;
    while (lo < hi) {
        int mid = (lo + hi) >> 1;
        if (a[mid] < key) lo = mid + 1; else hi = mid;
    }
    return lo;
}

__global__ void __launch_bounds__(64) fc_kernel(
    const int* __restrict__ batch,
    const float* __restrict__ fcw, const float* __restrict__ fcb,
    float* __restrict__ out)
{
    int g = blockIdx.x;
    int tid = threadIdx.x;

    __shared__ float pooled[64];
    __shared__ int s_cnt;
    if (tid == 0) s_cnt = lbound_i(batch, N_NODES, g + 1) - lbound_i(batch, N_NODES, g);
    __syncthreads();
    float inv = 1.f / (float)(s_cnt > 0 ? s_cnt : 1);
    pooled[tid] = g_pool[g * 64 + tid] * inv;
    __syncthreads();

    if (tid < OUT_DIM) {
        float o = fcb[tid];
#pragma unroll 8
        for (int k = 0; k < 64; k++) o = fmaf(pooled[k], fcw[k * OUT_DIM + tid], o);
        out[g * OUT_DIM + tid] = o;
    }
}

// ---------------- launcher ---------------------------------------------------
extern "C" void kernel_launch(void* const* d_in, const int* in_sizes, int n_in,
                              void* d_out, int out_size)
{
    const float* x     = (const float*)d_in[0];
    const int*   ei    = (const int*)d_in[1];     // [2, E] int32
    const int*   batch = (const int*)d_in[2];
    const float* w1i   = (const float*)d_in[3];
    const float* w1r   = (const float*)d_in[4];
    const float* b1    = (const float*)d_in[5];
    const float* w2i   = (const float*)d_in[6];
    const float* w2r   = (const float*)d_in[7];
    const float* b2    = (const float*)d_in[8];
    const float* fcw   = (const float*)d_in[9];
    const float* fcb   = (const float*)d_in[10];
    float*       out   = (float*)d_out;

    const int E = in_sizes[1] / 2;
    const int* row = ei;
    const int* col = ei + E;

    static bool s_init = false;
    static cudaStream_t s2;
    static cudaEvent_t evA, evB;
    if (!s_init) {
        cudaStreamCreateWithFlags(&s2, cudaStreamNonBlocking);
        cudaEventCreateWithFlags(&evA, cudaEventDisableTiming);
        cudaEventCreateWithFlags(&evB, cudaEventDisableTiming);
        cudaFuncSetAttribute(gemm_tc_kernel<float>,
                             cudaFuncAttributeMaxDynamicSharedMemorySize, GEMM_SMEM);
        cudaFuncSetAttribute(gemm_tc_kernel<__half>,
                             cudaFuncAttributeMaxDynamicSharedMemorySize, GEMM_SMEM);
        s_init = true;
    }

    void* degp = nullptr; void* poolp = nullptr; void* h1p = nullptr;
    cudaGetSymbolAddress(&degp, g_deg);
    cudaGetSymbolAddress(&poolp, g_pool);
    cudaGetSymbolAddress(&h1p, g_h1);

    cudaMemsetAsync(degp, 0, N_NODES * sizeof(int));
    cudaMemsetAsync(poolp, 0, NUM_GRAPHS * HDIM * sizeof(float));

    const int WPREP_BLOCKS = (WPREP_ELEMS + 511) / 512;
    count_wprep_kernel<<<EDGE_BLOCKS + WPREP_BLOCKS, 512>>>(col, E, w1i, w1r, w2i, w2r);
    scan_kernel<<<NB_SCAN, 256>>>();
    cudaEventRecord(evA, 0);

    // branch A (stream 0): fill CSR (L2-heavy)
    fill_csr_kernel<<<EDGE_BLOCKS, 512>>>(row, col, E);

    // branch B (s2): gemm1 (latency-bound, light L2)
    cudaStreamWaitEvent(s2, evA, 0);
    gemm_tc_kernel<float><<<GEMM_GRID, 256, GEMM_SMEM, s2>>>(x, 0, N_NODES);
    cudaEventRecord(evB, s2);

    // join
    cudaStreamWaitEvent(0, evB, 0);

    prop_combine_kernel<0><<<PROP_GRID, 256>>>(b1, batch);
    gemm_tc_kernel<__half><<<GEMM_GRID, 256, GEMM_SMEM>>>((const __half*)h1p, 1, N_NODES);
    prop_combine_kernel<1><<<PROP_GRID, 256>>>(b2, batch);
    fc_kernel<<<NUM_GRAPHS, 64>>>(batch, fcw, fcb, out);
}

// round 17
// speedup vs baseline: 1.0029x; 1.0029x over previous
#include <cuda_runtime.h>
#include <cuda_bf16.h>
#include <cuda_fp16.h>
#include <math.h>

// Problem constants (fixed by the dataset)
#define N_NODES   100000
#define E_EDGES   1600000
#define HDIM      64
#define OUT_DIM   32
#define NUM_GRAPHS 64

#define SCAN_TILE 1024
#define NB_SCAN   ((N_NODES + SCAN_TILE - 1) / SCAN_TILE)   // 98
#define EDGE_BLOCKS ((E_EDGES + 511) / 512)                  // 3125
#define PROP_GRID  ((N_NODES * 32 + 255) / 256)              // 12500
#define SCAN_FLAG  (1 << 30)

// tensor GEMM geometry (mma.sync path)
#define TILE_M    64             // per-iteration M tile
#define N2        128            // Wi|Wr side by side
#define KSTEPS    4              // 4 k-steps of 16 over K=64, x2 B segments
#define A_STRIDE  72             // bf16 elems per A row (64 + 8 pad)
#define B_STRIDE  136            // bf16 elems per B n-row (128 k + 8 pad)
#define A_BYTES   (TILE_M * A_STRIDE * 2)     // 9216
#define B_BYTES   (N2 * B_STRIDE * 2)         // 34816
#define GEMM_SMEM (A_BYTES + B_BYTES)         // 44032
#define GEMM_TILES ((N_NODES + TILE_M - 1) / TILE_M)   // 1563
#define GEMM_GRID  592           // persistent: 4 CTAs/SM x 148 SMs
#define WPREP_ELEMS (2 * N2 * B_STRIDE)

// ---------------- scratch (static device globals; no allocation) ------------
__device__ int   g_deg[N_NODES];
__device__ int   g_rowptr[N_NODES + 1];
__device__ int   g_bsums[NB_SCAN];
__device__ int   g_csr[E_EDGES];
__device__ int   g_perm[E_EDGES];
__device__ __align__(16) float  g_dinv[N_NODES];
__device__ __align__(16) __half g_t [N_NODES * HDIM];    // fp16 propagate source
__device__ __align__(16) __half g_r [N_NODES * HDIM];    // fp16 root term
__device__ __align__(16) __half g_h1[N_NODES * HDIM];    // fp16 layer-1 output
__device__ __align__(16) float  g_pool[NUM_GRAPHS * HDIM];
__device__ __align__(16) unsigned short g_wb[2][N2 * B_STRIDE];  // n-major B images

// ---------------- PTX helpers ------------------------------------------------
__device__ __forceinline__ unsigned smem_u32(const void* p) {
    unsigned a;
    asm("{ .reg .u64 t; cvta.to.shared.u64 t, %1; cvt.u32.u64 %0, t; }" : "=r"(a) : "l"(p));
    return a;
}
__device__ __forceinline__ void ldsm_x4(unsigned& r0, unsigned& r1, unsigned& r2, unsigned& r3,
                                        unsigned addr) {
    asm volatile("ldmatrix.sync.aligned.m8n8.x4.shared.b16 {%0,%1,%2,%3}, [%4];"
                 : "=r"(r0), "=r"(r1), "=r"(r2), "=r"(r3) : "r"(addr));
}
__device__ __forceinline__ void mma_bf16(float* d, const unsigned* a, const unsigned* b) {
    asm volatile(
        "mma.sync.aligned.m16n8k16.row.col.f32.bf16.bf16.f32 "
        "{%0,%1,%2,%3}, {%4,%5,%6,%7}, {%8,%9}, {%0,%1,%2,%3};"
        : "+f"(d[0]), "+f"(d[1]), "+f"(d[2]), "+f"(d[3])
        : "r"(a[0]), "r"(a[1]), "r"(a[2]), "r"(a[3]), "r"(b[0]), "r"(b[1]));
}

// ---------------- count_deg + wprep + bsums-clear (disjoint blocks) ----------
__global__ void __launch_bounds__(512) count_wprep_kernel(
    const int* __restrict__ col, int E,
    const float* __restrict__ w1i, const float* __restrict__ w1r,
    const float* __restrict__ w2i, const float* __restrict__ w2r)
{
    int b = blockIdx.x;
    if (b < EDGE_BLOCKS) {
        int i = b * 512 + threadIdx.x;
        if (i < E) g_perm[i] = atomicAdd(&g_deg[col[i]], 1);
    } else {
        int idx = (b - EDGE_BLOCKS) * 512 + threadIdx.x;
        if (b == EDGE_BLOCKS && threadIdx.x < NB_SCAN) g_bsums[threadIdx.x] = 0;
        if (idx >= WPREP_ELEMS) return;
        int layer = idx / (N2 * B_STRIDE);
        int rem = idx % (N2 * B_STRIDE);
        int n = rem / B_STRIDE;        // output col (0..63 Wi, 64..127 Wr)
        int k = rem % B_STRIDE;        // 0..63 Bh, 64..127 Bl, >=128 pad
        __nv_bfloat16 val = __float2bfloat16(0.f);
        if (k < 128) {
            int seg = k >> 6, kk = k & 63;
            const float* W = (n < 64) ? (layer ? w2i : w1i) : (layer ? w2r : w1r);
            float w = W[kk * 64 + (n & 63)];
            __nv_bfloat16 hi = __float2bfloat16(w);
            val = seg ? __float2bfloat16(w - __bfloat162float(hi)) : hi;
        }
        g_wb[layer][rem] = *reinterpret_cast<unsigned short*>(&val);
    }
}

// ---------------- single-pass scan (publish + spin lookback) -----------------
__global__ void __launch_bounds__(256) scan_kernel() {
    int b = blockIdx.x;
    int tid = threadIdx.x;
    int lane = tid & 31, warp = tid >> 5;

    int base = b * SCAN_TILE + tid * 4;
    int d[4];
#pragma unroll
    for (int j = 0; j < 4; j++) {
        int idx = base + j;
        d[j] = (idx < N_NODES) ? g_deg[idx] : 0;
    }
    int tsum = d[0] + d[1] + d[2] + d[3];
    int incl = tsum;
    for (int o = 1; o < 32; o <<= 1) {
        int v = __shfl_up_sync(0xffffffffu, incl, o);
        if (lane >= o) incl += v;
    }
    __shared__ int wsum[8];
    if (lane == 31) wsum[warp] = incl;
    __syncthreads();

    if (tid == 0) {
        int total = 0;
        for (int w = 0; w < 8; w++) total += wsum[w];
        atomicExch(&g_bsums[b], total | SCAN_FLAG);
    }

    int pre = 0;
    if (tid < b) {
        volatile int* p = &g_bsums[tid];
        int v;
        do { v = *p; } while ((v & SCAN_FLAG) == 0);
        pre = v & ~SCAN_FLAG;
    }
    for (int o = 16; o > 0; o >>= 1) pre += __shfl_down_sync(0xffffffffu, pre, o);
    __shared__ int ws2[8];
    if (lane == 0) ws2[warp] = pre;
    __syncthreads();
    __shared__ int s_boff;
    if (tid == 0) {
        int t = 0;
        for (int w = 0; w < 8; w++) t += ws2[w];
        s_boff = t;
    }
    __syncthreads();

    int excl = incl - tsum;
    int woff = 0;
    for (int w = 0; w < warp; w++) woff += wsum[w];
    int off = s_boff + woff + excl;
#pragma unroll
    for (int j = 0; j < 4; j++) {
        int idx = base + j;
        if (idx < N_NODES) {
            g_rowptr[idx] = off;
            g_dinv[idx]   = (d[j] > 0) ? rsqrtf((float)d[j]) : 0.0f;
            off += d[j];
        }
    }
    if (b == NB_SCAN - 1 && tid == 255) g_rowptr[N_NODES] = off;
}

// atomic-free fill using precomputed slots
__global__ void __launch_bounds__(512) fill_csr_kernel(const int* __restrict__ row,
                                                       const int* __restrict__ col, int E) {
    int i = blockIdx.x * 512 + threadIdx.x;
    if (i < E) g_csr[g_rowptr[col[i]] + g_perm[i]] = row[i];
}

// ---------------- persistent mma.sync dual GEMM (4 CTAs/SM) ------------------
// Each CTA stages B once, then loops over 64-row M-tiles.
template <typename TIN>
__global__ void __launch_bounds__(256, 4) gemm_tc_kernel(
    const TIN* __restrict__ X, int layer, int n)
{
    extern __shared__ char dsm[];
    __nv_bfloat16* sA = (__nv_bfloat16*)dsm;             // [64][A_STRIDE]
    __nv_bfloat16* sB = (__nv_bfloat16*)(dsm + A_BYTES); // [128 n][B_STRIDE]

    int tid = threadIdx.x;
    int wid = tid >> 5, lane = tid & 31;

    // stage B' image once (35KB from L2)
    {
        const uint4* src = (const uint4*)g_wb[layer];
        uint4* dst = (uint4*)sB;
        for (int i = tid; i < B_BYTES / 16; i += 256) dst[i] = src[i];
    }

    int mwarp = (wid & 3) * 16;      // 16-row m-group
    int nwarp = (wid >> 2);          // 0 -> T cols, 1 -> R cols
    int nbase = nwarp * 64;

    unsigned aAbase, aBbase;
    {
        unsigned sAu = smem_u32(sA);
        unsigned sBu = smem_u32(sB);
        aAbase = sAu + (unsigned)((mwarp + (lane & 15)) * A_STRIDE * 2 + (lane >> 4) * 16);
        int brow = nbase + ((lane >> 4) & 1) * 8 + (lane & 7);
        int bcol = ((lane >> 3) & 1) * 8;
        aBbase = sBu + (unsigned)(brow * B_STRIDE * 2 + bcol * 2);
    }

    int ar = tid >> 2;               // A-convert: row 0..63
    int kq = tid & 3;                // k quarter
    unsigned* arow = (unsigned*)(sA + ar * A_STRIDE);

    for (int tile = blockIdx.x; tile < GEMM_TILES; tile += GEMM_GRID) {
        int row0 = tile * TILE_M;

        __syncthreads();   // prior iteration's mainloop done before sA overwrite

        // convert A rows -> Ah bf16 (4 threads per row, 16 k-elems each)
        {
            int grow = row0 + ar;
            if (sizeof(TIN) == 4) {
                const float4* x4 = (const float4*)X;
#pragma unroll
                for (int q = 0; q < 4; q++) {
                    float4 v = make_float4(0.f, 0.f, 0.f, 0.f);
                    if (grow < n) v = x4[(size_t)grow * 16 + kq * 4 + q];
                    int k0 = kq * 16 + q * 4;
#pragma unroll
                    for (int h = 0; h < 2; h++) {
                        float a = h ? v.z : v.x;
                        float b = h ? v.w : v.y;
                        __nv_bfloat162 ph;
                        ph.x = __float2bfloat16(a);
                        ph.y = __float2bfloat16(b);
                        arow[(k0 + h * 2) >> 1] = *reinterpret_cast<unsigned*>(&ph);
                    }
                }
            } else {
                const uint4* x4 = (const uint4*)X;       // 8 halves per uint4
#pragma unroll
                for (int q = 0; q < 2; q++) {
                    uint4 v = make_uint4(0u, 0u, 0u, 0u);
                    if (grow < n) v = x4[(size_t)grow * 8 + kq * 2 + q];
                    unsigned comp[4] = {v.x, v.y, v.z, v.w};
                    int k0 = kq * 16 + q * 8;
#pragma unroll
                    for (int u = 0; u < 4; u++) {
                        __half2 hv = *reinterpret_cast<__half2*>(&comp[u]);
                        float2 f = __half22float2(hv);
                        __nv_bfloat162 ph;
                        ph.x = __float2bfloat16(f.x);
                        ph.y = __float2bfloat16(f.y);
                        arow[(k0 + u * 2) >> 1] = *reinterpret_cast<unsigned*>(&ph);
                    }
                }
            }
        }
        __syncthreads();

        float acc[8][4];
#pragma unroll
        for (int j = 0; j < 8; j++)
#pragma unroll
            for (int c = 0; c < 4; c++) acc[j][c] = 0.f;

#pragma unroll
        for (int ks = 0; ks < KSTEPS; ks++) {
            unsigned a[4];
            ldsm_x4(a[0], a[1], a[2], a[3], aAbase + (unsigned)(ks * 32));
#pragma unroll
            for (int seg = 0; seg < 2; seg++) {
                unsigned b[8][2];
#pragma unroll
                for (int j = 0; j < 4; j++) {
                    unsigned r0, r1, r2, r3;
                    ldsm_x4(r0, r1, r2, r3,
                            aBbase + (unsigned)(j * 16 * B_STRIDE * 2 + (seg * 64 + ks * 16) * 2));
                    b[2 * j][0] = r0; b[2 * j][1] = r1;
                    b[2 * j + 1][0] = r2; b[2 * j + 1][1] = r3;
                }
#pragma unroll
                for (int j = 0; j < 8; j++)
                    mma_bf16(acc[j], a, b[j]);
            }
        }

        // epilogue: T (dinv-scaled, fp16) and R (fp16)
        {
            int r0 = row0 + mwarp + (lane >> 2);
            int r1 = r0 + 8;
            if (nwarp == 0) {
                float dv0 = (r0 < n) ? g_dinv[r0] : 0.f;
                float dv1 = (r1 < n) ? g_dinv[r1] : 0.f;
#pragma unroll
                for (int j = 0; j < 8; j++) {
                    int c = j * 8 + (lane & 3) * 2;
                    if (r0 < n)
                        *(__half2*)(g_t + (size_t)r0 * 64 + c) =
                            __floats2half2_rn(acc[j][0] * dv0, acc[j][1] * dv0);
                    if (r1 < n)
                        *(__half2*)(g_t + (size_t)r1 * 64 + c) =
                            __floats2half2_rn(acc[j][2] * dv1, acc[j][3] * dv1);
                }
            } else {
#pragma unroll
                for (int j = 0; j < 8; j++) {
                    int c = j * 8 + (lane & 3) * 2;
                    if (r0 < n)
                        *(__half2*)(g_r + (size_t)r0 * 64 + c) =
                            __floats2half2_rn(acc[j][0], acc[j][1]);
                    if (r1 < n)
                        *(__half2*)(g_r + (size_t)r1 * 64 + c) =
                            __floats2half2_rn(acc[j][2], acc[j][3]);
                }
            }
        }
    }
}

// ---------------- propagate + root + bias + relu (+ pool) -------------------
template <int LAYER>
__global__ void __launch_bounds__(256) prop_combine_kernel(
    const float* __restrict__ bias, const int* __restrict__ batch)
{
    __shared__ float pacc[64];
    int tid = threadIdx.x;
    if (LAYER == 1) {
        if (tid < 64) pacc[tid] = 0.f;
        __syncthreads();
    }

    int warp = (blockIdx.x * blockDim.x + tid) >> 5;
    int lane = tid & 31;
    int node = warp;

    if (node < N_NODES) {
        int s = g_rowptr[node];
        int e = g_rowptr[node + 1];

        const __half2* T2 = (const __half2*)g_t;
        float2 acc0 = make_float2(0.f, 0.f);
        float2 acc1 = make_float2(0.f, 0.f);
        float2 acc2 = make_float2(0.f, 0.f);
        float2 acc3 = make_float2(0.f, 0.f);

        int i = s;
        for (; i + 3 < e; i += 4) {
            int s0 = __ldg(&g_csr[i]);
            int s1 = __ldg(&g_csr[i + 1]);
            int s2 = __ldg(&g_csr[i + 2]);
            int s3 = __ldg(&g_csr[i + 3]);
            float2 v0 = __half22float2(T2[(size_t)s0 * 32 + lane]);
            float2 v1 = __half22float2(T2[(size_t)s1 * 32 + lane]);
            float2 v2 = __half22float2(T2[(size_t)s2 * 32 + lane]);
            float2 v3 = __half22float2(T2[(size_t)s3 * 32 + lane]);
            acc0.x += v0.x; acc0.y += v0.y;
            acc1.x += v1.x; acc1.y += v1.y;
            acc2.x += v2.x; acc2.y += v2.y;
            acc3.x += v3.x; acc3.y += v3.y;
        }
        for (; i < e; i++) {
            int s0 = __ldg(&g_csr[i]);
            float2 v0 = __half22float2(T2[(size_t)s0 * 32 + lane]);
            acc0.x += v0.x; acc0.y += v0.y;
        }
        acc0.x += acc1.x + acc2.x + acc3.x;
        acc0.y += acc1.y + acc2.y + acc3.y;

        float dv = g_dinv[node];
        float2 r = __half22float2(((const __half2*)g_r)[(size_t)node * 32 + lane]);
        float bx = bias[2 * lane], by = bias[2 * lane + 1];
        float hx = fmaf(dv, acc0.x, r.x + bx);
        float hy = fmaf(dv, acc0.y, r.y + by);
        hx = hx > 0.f ? hx : 0.f;
        hy = hy > 0.f ? hy : 0.f;

        if (LAYER == 0) {
            ((__half2*)g_h1)[(size_t)node * 32 + lane] = __floats2half2_rn(hx, hy);
        } else {
            int gme = __ldg(&batch[node]);
            int g0  = __ldg(&batch[blockIdx.x * 8]);
            if (gme == g0) {
                atomicAdd(&pacc[2 * lane], hx);
                atomicAdd(&pacc[2 * lane + 1], hy);
            } else {
                atomicAdd(&g_pool[gme * 64 + 2 * lane], hx);
                atomicAdd(&g_pool[gme * 64 + 2 * lane + 1], hy);
            }
        }
    }

    if (LAYER == 1) {
        __syncthreads();
        if (tid < 64) {
            int g0 = __ldg(&batch[blockIdx.x * 8]);
            atomicAdd(&g_pool[g0 * 64 + tid], pacc[tid]);
        }
    }
}

// ---------------- final FC on pooled means -----------------------------------
__device__ __forceinline__ int lbound_i(const int* a, int n, int key) {
    int lo = 0, hi = n;
    while (lo < hi) {
        int mid = (lo + hi) >> 1;
        if (a[mid] < key) lo = mid + 1; else hi = mid;
    }
    return lo;
}

__global__ void __launch_bounds__(64) fc_kernel(
    const int* __restrict__ batch,
    const float* __restrict__ fcw, const float* __restrict__ fcb,
    float* __restrict__ out)
{
    int g = blockIdx.x;
    int tid = threadIdx.x;

    __shared__ float pooled[64];
    __shared__ int s_cnt;
    if (tid == 0) s_cnt = lbound_i(batch, N_NODES, g + 1) - lbound_i(batch, N_NODES, g);
    __syncthreads();
    float inv = 1.f / (float)(s_cnt > 0 ? s_cnt : 1);
    pooled[tid] = g_pool[g * 64 + tid] * inv;
    __syncthreads();

    if (tid < OUT_DIM) {
        float o = fcb[tid];
#pragma unroll 8
        for (int k = 0; k < 64; k++) o = fmaf(pooled[k], fcw[k * OUT_DIM + tid], o);
        out[g * OUT_DIM + tid] = o;
    }
}

// ---------------- launcher ---------------------------------------------------
extern "C" void kernel_launch(void* const* d_in, const int* in_sizes, int n_in,
                              void* d_out, int out_size)
{
    const float* x     = (const float*)d_in[0];
    const int*   ei    = (const int*)d_in[1];     // [2, E] int32
    const int*   batch = (const int*)d_in[2];
    const float* w1i   = (const float*)d_in[3];
    const float* w1r   = (const float*)d_in[4];
    const float* b1    = (const float*)d_in[5];
    const float* w2i   = (const float*)d_in[6];
    const float* w2r   = (const float*)d_in[7];
    const float* b2    = (const float*)d_in[8];
    const float* fcw   = (const float*)d_in[9];
    const float* fcb   = (const float*)d_in[10];
    float*       out   = (float*)d_out;

    const int E = in_sizes[1] / 2;
    const int* row = ei;
    const int* col = ei + E;

    static bool s_init = false;
    if (!s_init) {
        cudaFuncSetAttribute(gemm_tc_kernel<float>,
                             cudaFuncAttributeMaxDynamicSharedMemorySize, GEMM_SMEM);
        cudaFuncSetAttribute(gemm_tc_kernel<__half>,
                             cudaFuncAttributeMaxDynamicSharedMemorySize, GEMM_SMEM);
        s_init = true;
    }

    void* degp = nullptr; void* poolp = nullptr; void* h1p = nullptr;
    cudaGetSymbolAddress(&degp, g_deg);
    cudaGetSymbolAddress(&poolp, g_pool);
    cudaGetSymbolAddress(&h1p, g_h1);

    cudaMemsetAsync(degp, 0, N_NODES * sizeof(int));
    cudaMemsetAsync(poolp, 0, NUM_GRAPHS * HDIM * sizeof(float));

    const int WPREP_BLOCKS = (WPREP_ELEMS + 511) / 512;
    count_wprep_kernel<<<EDGE_BLOCKS + WPREP_BLOCKS, 512>>>(col, E, w1i, w1r, w2i, w2r);
    scan_kernel<<<NB_SCAN, 256>>>();
    fill_csr_kernel<<<EDGE_BLOCKS, 512>>>(row, col, E);

    // layer 1
    gemm_tc_kernel<float><<<GEMM_GRID, 256, GEMM_SMEM>>>(x, 0, N_NODES);
    prop_combine_kernel<0><<<PROP_GRID, 256>>>(b1, batch);
    // layer 2
    gemm_tc_kernel<__half><<<GEMM_GRID, 256, GEMM_SMEM>>>((const __half*)h1p, 1, N_NODES);
    prop_combine_kernel<1><<<PROP_GRID, 256>>>(b2, batch);
    // final FC
    fc_kernel<<<NUM_GRAPHS, 64>>>(batch, fcw, fcb, out);
}